// round 10
// baseline (speedup 1.0000x reference)
#include <cuda_runtime.h>
#include <cuda_bf16.h>
#include <cstdint>

#define BATCH 2
#define NC 4096
#define NF 16384
#define CC 256
#define CF 128
#define CO 256
#define KTOT 384  // CC + CF
#define NBLKF (NF / 128)

// NN split config: 4 points/thread, 256-pt chunks
#define NN_TPB 256
#define NN_PPT 4
#define NN_PTS (NN_TPB * NN_PPT)      // 1024 fine points per block
#define NN_CHK 256                    // coarse points per chunk
#define NN_NCHUNK (NC / NN_CHK)       // 16

typedef unsigned long long u64;

// ---------------- scratch (device globals; no allocations allowed) ----------
__device__ float g_Yc[BATCH * CO * NC];   // Wc @ Fc : [B, Co, Nc]
__device__ int   g_idx[BATCH * NF];
__device__ u64   g_nn_part[BATCH * NN_NCHUNK * NF];
__device__ float g_ps [BATCH * CO * NBLKF];
__device__ float g_pss[BATCH * CO * NBLKF];
__device__ float g_scale[CO];
__device__ float g_shift[CO];
// pre-split bf16 operands (same layouts as fp32 originals)
__device__ __nv_bfloat16 g_Whi[CO * KTOT];
__device__ __nv_bfloat16 g_Wlo[CO * KTOT];
__device__ __nv_bfloat16 g_Ffh[BATCH * CF * NF];
__device__ __nv_bfloat16 g_Ffl[BATCH * CF * NF];
__device__ __nv_bfloat16 g_Fch[BATCH * CC * NC];
__device__ __nv_bfloat16 g_Fcl[BATCH * CC * NC];

// ---------------- helpers ----------------------------------------------------
__device__ __forceinline__ uint32_t smem_u32(const void* p) {
    uint32_t a;
    asm("{ .reg .u64 t; cvta.to.shared.u64 t, %1; cvt.u32.u64 %0, t; }"
        : "=r"(a) : "l"(p));
    return a;
}
__device__ __forceinline__ void cp16(uint32_t dst, const void* src) {
    asm volatile("cp.async.cg.shared.global [%0], [%1], 16;"
                 :: "r"(dst), "l"(src));
}
#define CP_COMMIT() asm volatile("cp.async.commit_group;" ::: "memory")
#define CP_WAIT1()  asm volatile("cp.async.wait_group 1;" ::: "memory")
#define CP_WAIT0()  asm volatile("cp.async.wait_group 0;" ::: "memory")

__device__ __forceinline__ void ldsm4(uint32_t (&r)[4], uint32_t addr) {
    asm volatile("ldmatrix.sync.aligned.m8n8.x4.shared.b16 {%0,%1,%2,%3}, [%4];"
                 : "=r"(r[0]), "=r"(r[1]), "=r"(r[2]), "=r"(r[3]) : "r"(addr));
}
__device__ __forceinline__ void ldsm4t(uint32_t (&r)[4], uint32_t addr) {
    asm volatile("ldmatrix.sync.aligned.m8n8.x4.trans.shared.b16 {%0,%1,%2,%3}, [%4];"
                 : "=r"(r[0]), "=r"(r[1]), "=r"(r[2]), "=r"(r[3]) : "r"(addr));
}
__device__ __forceinline__ void mma16816(float (&d)[4], const uint32_t (&a)[4],
                                         uint32_t b0, uint32_t b1) {
    asm volatile(
        "mma.sync.aligned.m16n8k16.row.col.f32.bf16.bf16.f32 "
        "{%0,%1,%2,%3}, {%4,%5,%6,%7}, {%8,%9}, {%0,%1,%2,%3};"
        : "+f"(d[0]), "+f"(d[1]), "+f"(d[2]), "+f"(d[3])
        : "r"(a[0]), "r"(a[1]), "r"(a[2]), "r"(a[3]), "r"(b0), "r"(b1));
}

__device__ __forceinline__ void split2(float x0, float x1, uint32_t& hi, uint32_t& lo) {
    __nv_bfloat16 h0 = __float2bfloat16(x0);
    __nv_bfloat16 h1 = __float2bfloat16(x1);
    float r0 = x0 - __bfloat162float(h0);
    float r1 = x1 - __bfloat162float(h1);
    __nv_bfloat162 hh;
    hh.x = h0; hh.y = h1;
    __nv_bfloat162 ll;
    ll.x = __float2bfloat16(r0); ll.y = __float2bfloat16(r1);
    hi = *(uint32_t*)&hh;
    lo = *(uint32_t*)&ll;
}

// monotone float -> orderable u32 (neg floats map below pos floats)
__device__ __forceinline__ uint32_t fkey(float d) {
    uint32_t u = __float_as_uint(d);
    return (u & 0x80000000u) ? ~u : (u | 0x80000000u);
}
__device__ __forceinline__ u64 packdi(float d, int idx) {
    return ((u64)fkey(d) << 32) | (uint32_t)idx;
}

// ============================================================================
// K0: split fp32 -> bf16 hi/lo (same layout). which: 0=W, 1=Ff, 2=Fc
// ============================================================================
__global__ void split_kernel(const float4* __restrict__ src, int which) {
    const int i = blockIdx.x * 256 + threadIdx.x;
    uint2* hi;
    uint2* lo;
    if (which == 0)      { hi = (uint2*)g_Whi; lo = (uint2*)g_Wlo; }
    else if (which == 1) { hi = (uint2*)g_Ffh; lo = (uint2*)g_Ffl; }
    else                 { hi = (uint2*)g_Fch; lo = (uint2*)g_Fcl; }
    float4 v = src[i];
    uint32_t h0, l0, h1, l1;
    split2(v.x, v.y, h0, l0);
    split2(v.z, v.w, h1, l1);
    hi[i] = make_uint2(h0, h1);
    lo[i] = make_uint2(l0, l1);
}

// ============================================================================
// K1a: NN partial argmin. grid (NF/NN_PTS, NN_NCHUNK, B), 256 threads.
// Each thread: 4 fine points vs one 256-pt coarse chunk in smem.
// d(p,c) = |c|^2 - 2 p.c  (same argmin as euclidean).
// ============================================================================
__global__ __launch_bounds__(NN_TPB) void nn_part_kernel(
    const float* __restrict__ xyzc, const float* __restrict__ xyzf) {
    __shared__ float4 sc[NN_CHK];
    const int b = blockIdx.z;
    const int chunk = blockIdx.y;
    const int t = threadIdx.x;
    const int fbase = blockIdx.x * NN_PTS + t;

    float px[NN_PPT], py[NN_PPT], pz[NN_PPT];
#pragma unroll
    for (int p = 0; p < NN_PPT; p++) {
        const float* pp = xyzf + ((size_t)b * NF + fbase + p * NN_TPB) * 3;
        px[p] = -2.0f * pp[0];
        py[p] = -2.0f * pp[1];
        pz[p] = -2.0f * pp[2];
    }

    // load chunk: 256 points, one per thread
    {
        const float* c = xyzc + ((size_t)b * NC + chunk * NN_CHK + t) * 3;
        float x = c[0], y = c[1], z = c[2];
        sc[t] = make_float4(x, y, z, x * x + y * y + z * z);
    }
    __syncthreads();

    float best[NN_PPT];
    int bi[NN_PPT];
#pragma unroll
    for (int p = 0; p < NN_PPT; p++) {
        best[p] = 3.4e38f;
        bi[p] = 0;
    }

#pragma unroll 2
    for (int j = 0; j < NN_CHK; j += 4) {
        float4 c0 = sc[j];
        float4 c1 = sc[j + 1];
        float4 c2 = sc[j + 2];
        float4 c3 = sc[j + 3];
#pragma unroll
        for (int p = 0; p < NN_PPT; p++) {
            float d0 = fmaf(pz[p], c0.z, fmaf(py[p], c0.y, fmaf(px[p], c0.x, c0.w)));
            float d1 = fmaf(pz[p], c1.z, fmaf(py[p], c1.y, fmaf(px[p], c1.x, c1.w)));
            float d2 = fmaf(pz[p], c2.z, fmaf(py[p], c2.y, fmaf(px[p], c2.x, c2.w)));
            float d3 = fmaf(pz[p], c3.z, fmaf(py[p], c3.y, fmaf(px[p], c3.x, c3.w)));
            float m = fminf(fminf(d0, d1), fminf(d2, d3));
            if (m < best[p]) {  // rare; resolve first index inside
                best[p] = m;
                int jj = (d0 == m) ? 0 : (d1 == m) ? 1 : (d2 == m) ? 2 : 3;
                bi[p] = j + jj;
            }
        }
    }

    const int cbase = chunk * NN_CHK;
    u64* part = g_nn_part + ((size_t)b * NN_NCHUNK + chunk) * NF;
#pragma unroll
    for (int p = 0; p < NN_PPT; p++)
        part[fbase + p * NN_TPB] = packdi(best[p], cbase + bi[p]);
}

// ============================================================================
// K1b: combine partials. u64-min over chunks (min dist, ties -> min idx).
// ============================================================================
__global__ void nn_combine_kernel() {
    const int i = blockIdx.x * 256 + threadIdx.x;  // over B*NF
    const int b = i >> 14;
    const int f = i & (NF - 1);
    const u64* part = g_nn_part + (size_t)b * NN_NCHUNK * NF + f;
    u64 best = part[0];
#pragma unroll
    for (int c = 1; c < NN_NCHUNK; c++) {
        u64 v = part[(size_t)c * NF];
        best = (v < best) ? v : best;
    }
    g_idx[i] = (int)(best & 0xFFFFFFFFu);
}

// ============================================================================
// HMMA bf16 split GEMM, cp.async 2-stage pipeline on pre-split bf16 operands.
// (unchanged from R9 / 139.2us baseline)
// ============================================================================
#define AROW 40
#define BROW 136
#define OFF_AH 0
#define OFF_AL 10240
#define OFF_BH 20480
#define OFF_BL 29184
#define BUFSZ 37888
#define OSTR 132
#define SMEM_BYTES (2 * BUFSZ)

template <int N, int KDIM, int WOFF, bool GATHER>
__global__ __launch_bounds__(256) void hmma_gemm_kernel(float* __restrict__ dout) {
    extern __shared__ char smp[];
    const uint32_t sb = smem_u32(smp);
    __shared__ int sidx[128];
    constexpr int NCH = KDIM / 32;

    const int b = blockIdx.z;
    const int mBase = blockIdx.y * 128;
    const int nBase = blockIdx.x * 128;
    const int t = threadIdx.x;
    const int w = t >> 5;
    const int lid = t & 31;
    const int wm = (w >> 1) * 32;
    const int wn = (w & 1) * 64;

    if (GATHER && t < 128) sidx[t] = g_idx[b * NF + nBase + t];

    const __nv_bfloat16* Ahi = g_Whi;
    const __nv_bfloat16* Alo = g_Wlo;
    const __nv_bfloat16* Bhi = GATHER ? g_Ffh : g_Fch;
    const __nv_bfloat16* Blo = GATHER ? g_Ffl : g_Fcl;

    float c[2][8][4];
#pragma unroll
    for (int mt = 0; mt < 2; mt++)
#pragma unroll
        for (int nt = 0; nt < 8; nt++)
#pragma unroll
            for (int r = 0; r < 4; r++) c[mt][nt][r] = 0.f;

    const char* Abh = (const char*)(Ahi + (size_t)mBase * KTOT + WOFF);
    const char* Abl = (const char*)(Alo + (size_t)mBase * KTOT + WOFF);
    const char* Bbh = (const char*)(Bhi + ((size_t)b * KDIM) * N + nBase);
    const char* Bbl = (const char*)(Blo + ((size_t)b * KDIM) * N + nBase);

    const int ar0 = t >> 2;
    const int ac0 = t & 3;
    const int br0 = t >> 4;
    const int bc0 = t & 15;

    const int a_row = (lid & 7) + ((lid >> 3) & 1) * 8;
    const int a_colb = (lid >> 4) * 8;
    const int b_row = (lid & 7) + ((lid >> 3) & 1) * 8;
    const int b_colb = (lid >> 4) * 8;

    auto issue = [&](int s, int k0) {
        const uint32_t st = sb + s * BUFSZ;
#pragma unroll
        for (int p = 0; p < 2; p++) {
            const int row = ar0 + p * 64;
            const int col = ac0;
            cp16(st + OFF_AH + row * 80 + col * 16,
                 Abh + (size_t)row * (KTOT * 2) + k0 * 2 + col * 16);
            cp16(st + OFF_AL + row * 80 + col * 16,
                 Abl + (size_t)row * (KTOT * 2) + k0 * 2 + col * 16);
        }
#pragma unroll
        for (int p = 0; p < 2; p++) {
            const int k = br0 + p * 16;
            const int col = bc0;
            cp16(st + OFF_BH + k * 272 + col * 16,
                 Bbh + (size_t)(k0 + k) * (N * 2) + col * 16);
            cp16(st + OFF_BL + k * 272 + col * 16,
                 Bbl + (size_t)(k0 + k) * (N * 2) + col * 16);
        }
    };

    issue(0, 0);
    CP_COMMIT();

#pragma unroll
    for (int ck = 0; ck < NCH; ck++) {
        if (ck + 1 < NCH) {
            issue((ck + 1) & 1, (ck + 1) * 32);
            CP_COMMIT();
            CP_WAIT1();
        } else {
            CP_WAIT0();
        }
        __syncthreads();

        const uint32_t cb = sb + (ck & 1) * BUFSZ;
#pragma unroll
        for (int k16 = 0; k16 < 2; k16++) {
            uint32_t ah[2][4], al[2][4], bh[4][4], bl[4][4];
#pragma unroll
            for (int mt = 0; mt < 2; mt++) {
                uint32_t ad = cb + ((wm + mt * 16 + a_row) * AROW + k16 * 16 + a_colb) * 2;
                ldsm4(ah[mt], ad + OFF_AH);
                ldsm4(al[mt], ad + OFF_AL);
            }
#pragma unroll
            for (int ng = 0; ng < 4; ng++) {
                uint32_t bd = cb + ((k16 * 16 + b_row) * BROW + wn + ng * 16 + b_colb) * 2;
                ldsm4t(bh[ng], bd + OFF_BH);
                ldsm4t(bl[ng], bd + OFF_BL);
            }
#pragma unroll
            for (int mt = 0; mt < 2; mt++)
#pragma unroll
                for (int nt = 0; nt < 8; nt++) {
                    const int ng = nt >> 1;
                    const int pr = (nt & 1) * 2;
                    mma16816(c[mt][nt], ah[mt], bh[ng][pr], bh[ng][pr + 1]);
                    mma16816(c[mt][nt], ah[mt], bl[ng][pr], bl[ng][pr + 1]);
                    mma16816(c[mt][nt], al[mt], bh[ng][pr], bh[ng][pr + 1]);
                }
        }
        __syncthreads();
    }

    float* smOut = (float*)smp;
    {
        const int r_m = lid >> 2;
        const int cn = (lid & 3) * 2;
#pragma unroll
        for (int mt = 0; mt < 2; mt++)
#pragma unroll
            for (int nt = 0; nt < 8; nt++) {
                const int row = wm + mt * 16 + r_m;
                const int col = wn + nt * 8 + cn;
                *(float2*)&smOut[row * OSTR + col] =
                    make_float2(c[mt][nt][0], c[mt][nt][1]);
                *(float2*)&smOut[(row + 8) * OSTR + col] =
                    make_float2(c[mt][nt][2], c[mt][nt][3]);
            }
    }
    __syncthreads();

#pragma unroll 4
    for (int rr = 0; rr < 16; rr++) {
        const int r0 = w + rr * 8;
        const int m = mBase + r0;
        float4 v = *(float4*)&smOut[r0 * OSTR + lid * 4];
        if (GATHER) {
            const float* yc = g_Yc + ((size_t)b * CO + m) * NC;
            v.x += yc[sidx[lid * 4 + 0]];
            v.y += yc[sidx[lid * 4 + 1]];
            v.z += yc[sidx[lid * 4 + 2]];
            v.w += yc[sidx[lid * 4 + 3]];
            *(float4*)&dout[((size_t)b * CO + m) * NF + nBase + lid * 4] = v;
            float s = v.x + v.y + v.z + v.w;
            float ss = v.x * v.x + v.y * v.y + v.z * v.z + v.w * v.w;
#pragma unroll
            for (int off = 16; off > 0; off >>= 1) {
                s += __shfl_down_sync(0xffffffffu, s, off);
                ss += __shfl_down_sync(0xffffffffu, ss, off);
            }
            if (lid == 0) {
                g_ps [((size_t)b * CO + m) * NBLKF + blockIdx.x] = s;
                g_pss[((size_t)b * CO + m) * NBLKF + blockIdx.x] = ss;
            }
        } else {
            *(float4*)&g_Yc[((size_t)b * CO + m) * NC + nBase + lid * 4] = v;
        }
    }
}

// ============================================================================
// K4: finish BN stats from partials
// ============================================================================
__global__ void stats2_kernel(const float* __restrict__ gamma,
                              const float* __restrict__ beta) {
    const int o = blockIdx.x * 8 + (threadIdx.x >> 5);
    const int lane = threadIdx.x & 31;
    float s = 0.f, ss = 0.f;
#pragma unroll
    for (int j = 0; j < 8; j++) {
        int p = lane + j * 32;
        int b = p >> 7;
        int nblk = p & 127;
        size_t off = ((size_t)b * CO + o) * NBLKF + nblk;
        s += g_ps[off];
        ss += g_pss[off];
    }
#pragma unroll
    for (int off = 16; off > 0; off >>= 1) {
        s += __shfl_down_sync(0xffffffffu, s, off);
        ss += __shfl_down_sync(0xffffffffu, ss, off);
    }
    if (lane == 0) {
        const float invn = 1.0f / (BATCH * NF);
        float mean = s * invn;
        float var = ss * invn - mean * mean;
        var = fmaxf(var, 0.0f);
        float r = rsqrtf(var + 1e-5f);
        float sc = gamma[o] * r;
        g_scale[o] = sc;
        g_shift[o] = beta[o] - mean * sc;
    }
}

// ============================================================================
// K5: y = relu(y * scale + shift) in place
// ============================================================================
__global__ void norm_kernel(float* __restrict__ y) {
    const size_t i = (size_t)blockIdx.x * blockDim.x + threadIdx.x;
    const int o = (int)((i >> 12) & (CO - 1));
    const float sc = g_scale[o];
    const float sh = g_shift[o];
    float4 v = ((const float4*)y)[i];
    v.x = fmaxf(fmaf(v.x, sc, sh), 0.0f);
    v.y = fmaxf(fmaf(v.y, sc, sh), 0.0f);
    v.z = fmaxf(fmaf(v.z, sc, sh), 0.0f);
    v.w = fmaxf(fmaf(v.w, sc, sh), 0.0f);
    ((float4*)y)[i] = v;
}

// ============================================================================
extern "C" void kernel_launch(void* const* d_in, const int* in_sizes, int n_in,
                              void* d_out, int out_size) {
    const float* xyzc  = (const float*)d_in[0];  // [2, 4096, 3]
    const float* fc    = (const float*)d_in[1];  // [2, 256, 4096]
    const float* xyzf  = (const float*)d_in[2];  // [2, 16384, 3]
    const float* ff    = (const float*)d_in[3];  // [2, 128, 16384]
    const float* W     = (const float*)d_in[4];  // [256, 384]
    const float* gamma = (const float*)d_in[5];  // [256]
    const float* beta  = (const float*)d_in[6];  // [256]
    float* out = (float*)d_out;                  // [2, 256, 16384]

    (void)in_sizes; (void)n_in; (void)out_size;

    static bool attr_done = false;
    if (!attr_done) {
        cudaFuncSetAttribute(hmma_gemm_kernel<NC, CC, 0, false>,
                             cudaFuncAttributeMaxDynamicSharedMemorySize, SMEM_BYTES);
        cudaFuncSetAttribute(hmma_gemm_kernel<NF, CF, CC, true>,
                             cudaFuncAttributeMaxDynamicSharedMemorySize, SMEM_BYTES);
        attr_done = true;
    }

    // operand pre-split (fp32 -> bf16 hi/lo, same layouts)
    split_kernel<<<CO * KTOT / 1024, 256>>>((const float4*)W, 0);
    split_kernel<<<BATCH * CF * NF / 1024, 256>>>((const float4*)ff, 1);
    split_kernel<<<BATCH * CC * NC / 1024, 256>>>((const float4*)fc, 2);

    // NN: partial argmin over coarse chunks, then combine
    nn_part_kernel<<<dim3(NF / NN_PTS, NN_NCHUNK, BATCH), NN_TPB>>>(xyzc, xyzf);
    nn_combine_kernel<<<BATCH * NF / 256, 256>>>();

    // Yc = Wc @ Fc
    hmma_gemm_kernel<NC, CC, 0, false>
        <<<dim3(NC / 128, CO / 128, BATCH), 256, SMEM_BYTES>>>(out);

    // y = Wf @ Ff + gather(Yc), fused BN partials
    hmma_gemm_kernel<NF, CF, CC, true>
        <<<dim3(NF / 128, CO / 128, BATCH), 256, SMEM_BYTES>>>(out);

    stats2_kernel<<<CO / 8, 256>>>(gamma, beta);
    norm_kernel<<<(BATCH * CO * NF / 4) / 256, 256>>>(out);
}

// round 11
// speedup vs baseline: 1.0625x; 1.0625x over previous
#include <cuda_runtime.h>
#include <cuda_bf16.h>
#include <cstdint>

#define BATCH 2
#define NC 4096
#define NF 16384
#define CC 256
#define CF 128
#define CO 256
#define KTOT 384  // CC + CF
#define NBLKF (NF / 128)

// NN config: 4 points/thread, 256-pt chunks
#define NN_TPB 256
#define NN_PPT 4
#define NN_PTS (NN_TPB * NN_PPT)      // 1024 fine points per block
#define NN_CHK 256
#define NN_NCHUNK (NC / NN_CHK)       // 16
#define NN_BLOCKS 512                 // (NF/NN_PTS)=16 x 16 chunks x 2 batch

// split work (float4 counts)
#define W_F4   (CO * KTOT / 4)                    // 24576
#define FF_F4  (BATCH * CF * NF / 4)              // 1048576
#define FC_F4  (BATCH * CC * NC / 4)              // 524288
#define SPLIT_F4 (W_F4 + FF_F4 + FC_F4)           // 1597440
#define SPLIT_BLOCKS (SPLIT_F4 / 1024)            // 1560

typedef unsigned long long u64;

// ---------------- scratch (device globals; no allocations allowed) ----------
__device__ float g_Yc[BATCH * CO * NC];
__device__ int   g_idx[BATCH * NF];
__device__ u64   g_nn_part[BATCH * NN_NCHUNK * NF];
__device__ float g_ps [BATCH * CO * NBLKF];
__device__ float g_pss[BATCH * CO * NBLKF];
__device__ float g_scale[CO];
__device__ float g_shift[CO];
__device__ __nv_bfloat16 g_Whi[CO * KTOT];
__device__ __nv_bfloat16 g_Wlo[CO * KTOT];
__device__ __nv_bfloat16 g_Ffh[BATCH * CF * NF];
__device__ __nv_bfloat16 g_Ffl[BATCH * CF * NF];
__device__ __nv_bfloat16 g_Fch[BATCH * CC * NC];
__device__ __nv_bfloat16 g_Fcl[BATCH * CC * NC];

// ---------------- helpers ----------------------------------------------------
__device__ __forceinline__ uint32_t smem_u32(const void* p) {
    uint32_t a;
    asm("{ .reg .u64 t; cvta.to.shared.u64 t, %1; cvt.u32.u64 %0, t; }"
        : "=r"(a) : "l"(p));
    return a;
}
__device__ __forceinline__ void cp16(uint32_t dst, const void* src) {
    asm volatile("cp.async.cg.shared.global [%0], [%1], 16;"
                 :: "r"(dst), "l"(src));
}
#define CP_COMMIT() asm volatile("cp.async.commit_group;" ::: "memory")
#define CP_WAIT1()  asm volatile("cp.async.wait_group 1;" ::: "memory")
#define CP_WAIT0()  asm volatile("cp.async.wait_group 0;" ::: "memory")

__device__ __forceinline__ void ldsm4(uint32_t (&r)[4], uint32_t addr) {
    asm volatile("ldmatrix.sync.aligned.m8n8.x4.shared.b16 {%0,%1,%2,%3}, [%4];"
                 : "=r"(r[0]), "=r"(r[1]), "=r"(r[2]), "=r"(r[3]) : "r"(addr));
}
__device__ __forceinline__ void ldsm4t(uint32_t (&r)[4], uint32_t addr) {
    asm volatile("ldmatrix.sync.aligned.m8n8.x4.trans.shared.b16 {%0,%1,%2,%3}, [%4];"
                 : "=r"(r[0]), "=r"(r[1]), "=r"(r[2]), "=r"(r[3]) : "r"(addr));
}
__device__ __forceinline__ void mma16816(float (&d)[4], const uint32_t (&a)[4],
                                         uint32_t b0, uint32_t b1) {
    asm volatile(
        "mma.sync.aligned.m16n8k16.row.col.f32.bf16.bf16.f32 "
        "{%0,%1,%2,%3}, {%4,%5,%6,%7}, {%8,%9}, {%0,%1,%2,%3};"
        : "+f"(d[0]), "+f"(d[1]), "+f"(d[2]), "+f"(d[3])
        : "r"(a[0]), "r"(a[1]), "r"(a[2]), "r"(a[3]), "r"(b0), "r"(b1));
}

__device__ __forceinline__ void split2(float x0, float x1, uint32_t& hi, uint32_t& lo) {
    __nv_bfloat16 h0 = __float2bfloat16(x0);
    __nv_bfloat16 h1 = __float2bfloat16(x1);
    float r0 = x0 - __bfloat162float(h0);
    float r1 = x1 - __bfloat162float(h1);
    __nv_bfloat162 hh;
    hh.x = h0; hh.y = h1;
    __nv_bfloat162 ll;
    ll.x = __float2bfloat16(r0); ll.y = __float2bfloat16(r1);
    hi = *(uint32_t*)&hh;
    lo = *(uint32_t*)&ll;
}

__device__ __forceinline__ uint32_t fkey(float d) {
    uint32_t u = __float_as_uint(d);
    return (u & 0x80000000u) ? ~u : (u | 0x80000000u);
}
__device__ __forceinline__ u64 packdi(float d, int idx) {
    return ((u64)fkey(d) << 32) | (uint32_t)idx;
}

// ============================================================================
// GEMM body (template device fn): out[b,m,n] = sum_k W[m,WOFF+k]*F[b,k,n]
// bf16 split hi*hi + hi*lo + lo*hi, fp32 accum, cp.async 2-stage pipeline.
// ============================================================================
#define AROW 40
#define BROW 136
#define OFF_AH 0
#define OFF_AL 10240
#define OFF_BH 20480
#define OFF_BL 29184
#define BUFSZ 37888
#define OSTR 132
#define SMEM_BYTES (2 * BUFSZ + 512)  // + sidx

template <int N, int KDIM, int WOFF, bool GATHER>
__device__ __forceinline__ void gemm_body(int nb, int mb, int bb,
                                          float* __restrict__ dout, char* smp) {
    const uint32_t sb = smem_u32(smp);
    int* sidx = (int*)(smp + 2 * BUFSZ);
    constexpr int NCH = KDIM / 32;

    const int b = bb;
    const int mBase = mb * 128;
    const int nBase = nb * 128;
    const int t = threadIdx.x;
    const int w = t >> 5;
    const int lid = t & 31;
    const int wm = (w >> 1) * 32;
    const int wn = (w & 1) * 64;

    if (GATHER && t < 128) sidx[t] = g_idx[b * NF + nBase + t];

    const __nv_bfloat16* Ahi = g_Whi;
    const __nv_bfloat16* Alo = g_Wlo;
    const __nv_bfloat16* Bhi = GATHER ? g_Ffh : g_Fch;
    const __nv_bfloat16* Blo = GATHER ? g_Ffl : g_Fcl;

    float c[2][8][4];
#pragma unroll
    for (int mt = 0; mt < 2; mt++)
#pragma unroll
        for (int nt = 0; nt < 8; nt++)
#pragma unroll
            for (int r = 0; r < 4; r++) c[mt][nt][r] = 0.f;

    const char* Abh = (const char*)(Ahi + (size_t)mBase * KTOT + WOFF);
    const char* Abl = (const char*)(Alo + (size_t)mBase * KTOT + WOFF);
    const char* Bbh = (const char*)(Bhi + ((size_t)b * KDIM) * N + nBase);
    const char* Bbl = (const char*)(Blo + ((size_t)b * KDIM) * N + nBase);

    const int ar0 = t >> 2;
    const int ac0 = t & 3;
    const int br0 = t >> 4;
    const int bc0 = t & 15;

    const int a_row = (lid & 7) + ((lid >> 3) & 1) * 8;
    const int a_colb = (lid >> 4) * 8;
    const int b_row = (lid & 7) + ((lid >> 3) & 1) * 8;
    const int b_colb = (lid >> 4) * 8;

    auto issue = [&](int s, int k0) {
        const uint32_t st = sb + s * BUFSZ;
#pragma unroll
        for (int p = 0; p < 2; p++) {
            const int row = ar0 + p * 64;
            const int col = ac0;
            cp16(st + OFF_AH + row * 80 + col * 16,
                 Abh + (size_t)row * (KTOT * 2) + k0 * 2 + col * 16);
            cp16(st + OFF_AL + row * 80 + col * 16,
                 Abl + (size_t)row * (KTOT * 2) + k0 * 2 + col * 16);
        }
#pragma unroll
        for (int p = 0; p < 2; p++) {
            const int k = br0 + p * 16;
            const int col = bc0;
            cp16(st + OFF_BH + k * 272 + col * 16,
                 Bbh + (size_t)(k0 + k) * (N * 2) + col * 16);
            cp16(st + OFF_BL + k * 272 + col * 16,
                 Bbl + (size_t)(k0 + k) * (N * 2) + col * 16);
        }
    };

    issue(0, 0);
    CP_COMMIT();

#pragma unroll
    for (int ck = 0; ck < NCH; ck++) {
        if (ck + 1 < NCH) {
            issue((ck + 1) & 1, (ck + 1) * 32);
            CP_COMMIT();
            CP_WAIT1();
        } else {
            CP_WAIT0();
        }
        __syncthreads();

        const uint32_t cb = sb + (ck & 1) * BUFSZ;
#pragma unroll
        for (int k16 = 0; k16 < 2; k16++) {
            uint32_t ah[2][4], al[2][4], bh[4][4], bl[4][4];
#pragma unroll
            for (int mt = 0; mt < 2; mt++) {
                uint32_t ad = cb + ((wm + mt * 16 + a_row) * AROW + k16 * 16 + a_colb) * 2;
                ldsm4(ah[mt], ad + OFF_AH);
                ldsm4(al[mt], ad + OFF_AL);
            }
#pragma unroll
            for (int ng = 0; ng < 4; ng++) {
                uint32_t bd = cb + ((k16 * 16 + b_row) * BROW + wn + ng * 16 + b_colb) * 2;
                ldsm4t(bh[ng], bd + OFF_BH);
                ldsm4t(bl[ng], bd + OFF_BL);
            }
#pragma unroll
            for (int mt = 0; mt < 2; mt++)
#pragma unroll
                for (int nt = 0; nt < 8; nt++) {
                    const int ng = nt >> 1;
                    const int pr = (nt & 1) * 2;
                    mma16816(c[mt][nt], ah[mt], bh[ng][pr], bh[ng][pr + 1]);
                    mma16816(c[mt][nt], ah[mt], bl[ng][pr], bl[ng][pr + 1]);
                    mma16816(c[mt][nt], al[mt], bh[ng][pr], bh[ng][pr + 1]);
                }
        }
        __syncthreads();
    }

    // epilogue: accum -> smem [128][OSTR] -> coalesced global
    float* smOut = (float*)smp;
    {
        const int r_m = lid >> 2;
        const int cn = (lid & 3) * 2;
#pragma unroll
        for (int mt = 0; mt < 2; mt++)
#pragma unroll
            for (int nt = 0; nt < 8; nt++) {
                const int row = wm + mt * 16 + r_m;
                const int col = wn + nt * 8 + cn;
                *(float2*)&smOut[row * OSTR + col] =
                    make_float2(c[mt][nt][0], c[mt][nt][1]);
                *(float2*)&smOut[(row + 8) * OSTR + col] =
                    make_float2(c[mt][nt][2], c[mt][nt][3]);
            }
    }
    __syncthreads();

#pragma unroll 4
    for (int rr = 0; rr < 16; rr++) {
        const int r0 = w + rr * 8;
        const int m = mBase + r0;
        float4 v = *(float4*)&smOut[r0 * OSTR + lid * 4];
        if (GATHER) {
            const float* yc = g_Yc + ((size_t)b * CO + m) * NC;
            v.x += yc[sidx[lid * 4 + 0]];
            v.y += yc[sidx[lid * 4 + 1]];
            v.z += yc[sidx[lid * 4 + 2]];
            v.w += yc[sidx[lid * 4 + 3]];
            *(float4*)&dout[((size_t)b * CO + m) * NF + nBase + lid * 4] = v;
            float s = v.x + v.y + v.z + v.w;
            float ss = v.x * v.x + v.y * v.y + v.z * v.z + v.w * v.w;
#pragma unroll
            for (int off = 16; off > 0; off >>= 1) {
                s += __shfl_down_sync(0xffffffffu, s, off);
                ss += __shfl_down_sync(0xffffffffu, ss, off);
            }
            if (lid == 0) {
                g_ps [((size_t)b * CO + m) * NBLKF + nb] = s;
                g_pss[((size_t)b * CO + m) * NBLKF + nb] = ss;
            }
        } else {
            *(float4*)&g_Yc[((size_t)b * CO + m) * NC + nBase + lid * 4] = v;
        }
    }
}

// ============================================================================
// K_A: fused nn_part (blocks 0..511) + all operand splits (blocks 512..2071)
// ============================================================================
__global__ __launch_bounds__(256) void fusedA_kernel(
    const float* __restrict__ xyzc, const float* __restrict__ xyzf,
    const float* __restrict__ W, const float* __restrict__ ff,
    const float* __restrict__ fc) {
    const int bid = blockIdx.x;
    const int t = threadIdx.x;

    if (bid < NN_BLOCKS) {
        // ---- NN partial argmin
        __shared__ float4 sc[NN_CHK];
        const int fblk = bid & 15;
        const int chunk = (bid >> 4) & 15;
        const int b = bid >> 8;
        const int fbase = fblk * NN_PTS + t;

        float px[NN_PPT], py[NN_PPT], pz[NN_PPT];
#pragma unroll
        for (int p = 0; p < NN_PPT; p++) {
            const float* pp = xyzf + ((size_t)b * NF + fbase + p * NN_TPB) * 3;
            px[p] = -2.0f * pp[0];
            py[p] = -2.0f * pp[1];
            pz[p] = -2.0f * pp[2];
        }
        {
            const float* c = xyzc + ((size_t)b * NC + chunk * NN_CHK + t) * 3;
            float x = c[0], y = c[1], z = c[2];
            sc[t] = make_float4(x, y, z, x * x + y * y + z * z);
        }
        __syncthreads();

        float best[NN_PPT];
        int bi[NN_PPT];
#pragma unroll
        for (int p = 0; p < NN_PPT; p++) {
            best[p] = 3.4e38f;
            bi[p] = 0;
        }

#pragma unroll 2
        for (int j = 0; j < NN_CHK; j += 4) {
            float4 c0 = sc[j];
            float4 c1 = sc[j + 1];
            float4 c2 = sc[j + 2];
            float4 c3 = sc[j + 3];
#pragma unroll
            for (int p = 0; p < NN_PPT; p++) {
                float d0 = fmaf(pz[p], c0.z, fmaf(py[p], c0.y, fmaf(px[p], c0.x, c0.w)));
                float d1 = fmaf(pz[p], c1.z, fmaf(py[p], c1.y, fmaf(px[p], c1.x, c1.w)));
                float d2 = fmaf(pz[p], c2.z, fmaf(py[p], c2.y, fmaf(px[p], c2.x, c2.w)));
                float d3 = fmaf(pz[p], c3.z, fmaf(py[p], c3.y, fmaf(px[p], c3.x, c3.w)));
                float m = fminf(fminf(d0, d1), fminf(d2, d3));
                if (m < best[p]) {
                    best[p] = m;
                    int jj = (d0 == m) ? 0 : (d1 == m) ? 1 : (d2 == m) ? 2 : 3;
                    bi[p] = j + jj;
                }
            }
        }

        const int cbase = chunk * NN_CHK;
        u64* part = g_nn_part + ((size_t)b * NN_NCHUNK + chunk) * NF;
#pragma unroll
        for (int p = 0; p < NN_PPT; p++)
            part[fbase + p * NN_TPB] = packdi(best[p], cbase + bi[p]);
    } else {
        // ---- fp32 -> bf16 hi/lo splits (flat float4 range over W, Ff, Fc)
        const size_t base = (size_t)(bid - NN_BLOCKS) * 1024 + t;
#pragma unroll
        for (int r = 0; r < 4; r++) {
            size_t i = base + (size_t)r * 256;
            const float4* src;
            uint2* hi;
            uint2* lo;
            size_t off;
            if (i < W_F4) {
                src = (const float4*)W; hi = (uint2*)g_Whi; lo = (uint2*)g_Wlo;
                off = i;
            } else if (i < W_F4 + FF_F4) {
                src = (const float4*)ff; hi = (uint2*)g_Ffh; lo = (uint2*)g_Ffl;
                off = i - W_F4;
            } else {
                src = (const float4*)fc; hi = (uint2*)g_Fch; lo = (uint2*)g_Fcl;
                off = i - W_F4 - FF_F4;
            }
            float4 v = src[off];
            uint32_t h0, l0, h1, l1;
            split2(v.x, v.y, h0, l0);
            split2(v.z, v.w, h1, l1);
            hi[off] = make_uint2(h0, h1);
            lo[off] = make_uint2(l0, l1);
        }
    }
}

// ============================================================================
// K_B: fused coarse GEMM (blocks 0..127) + nn_combine (blocks 128..255)
// ============================================================================
__global__ __launch_bounds__(256) void fusedB_kernel(float* __restrict__ dout) {
    extern __shared__ char smp[];
    const int bid = blockIdx.x;
    if (bid < 128) {
        gemm_body<NC, CC, 0, false>(bid & 31, (bid >> 5) & 1, bid >> 6, dout, smp);
    } else {
        const int i = (bid - 128) * 256 + threadIdx.x;  // over B*NF
        const int b = i >> 14;
        const int f = i & (NF - 1);
        const u64* part = g_nn_part + (size_t)b * NN_NCHUNK * NF + f;
        u64 best = part[0];
#pragma unroll
        for (int c = 1; c < NN_NCHUNK; c++) {
            u64 v = part[(size_t)c * NF];
            best = (v < best) ? v : best;
        }
        g_idx[i] = (int)(best & 0xFFFFFFFFu);
    }
}

// ============================================================================
// K_C: fine GEMM + gather + BN partials
// ============================================================================
__global__ __launch_bounds__(256) void gemmC_kernel(float* __restrict__ dout) {
    extern __shared__ char smp[];
    gemm_body<NF, CF, CC, true>(blockIdx.x, blockIdx.y, blockIdx.z, dout, smp);
}

// ============================================================================
// K4: finish BN stats from partials
// ============================================================================
__global__ void stats2_kernel(const float* __restrict__ gamma,
                              const float* __restrict__ beta) {
    const int o = blockIdx.x * 8 + (threadIdx.x >> 5);
    const int lane = threadIdx.x & 31;
    float s = 0.f, ss = 0.f;
#pragma unroll
    for (int j = 0; j < 8; j++) {
        int p = lane + j * 32;
        int b = p >> 7;
        int nblk = p & 127;
        size_t off = ((size_t)b * CO + o) * NBLKF + nblk;
        s += g_ps[off];
        ss += g_pss[off];
    }
#pragma unroll
    for (int off = 16; off > 0; off >>= 1) {
        s += __shfl_down_sync(0xffffffffu, s, off);
        ss += __shfl_down_sync(0xffffffffu, ss, off);
    }
    if (lane == 0) {
        const float invn = 1.0f / (BATCH * NF);
        float mean = s * invn;
        float var = ss * invn - mean * mean;
        var = fmaxf(var, 0.0f);
        float r = rsqrtf(var + 1e-5f);
        float sc = gamma[o] * r;
        g_scale[o] = sc;
        g_shift[o] = beta[o] - mean * sc;
    }
}

// ============================================================================
// K5: y = relu(y * scale + shift) in place
// ============================================================================
__global__ void norm_kernel(float* __restrict__ y) {
    const size_t i = (size_t)blockIdx.x * blockDim.x + threadIdx.x;
    const int o = (int)((i >> 12) & (CO - 1));
    const float sc = g_scale[o];
    const float sh = g_shift[o];
    float4 v = ((const float4*)y)[i];
    v.x = fmaxf(fmaf(v.x, sc, sh), 0.0f);
    v.y = fmaxf(fmaf(v.y, sc, sh), 0.0f);
    v.z = fmaxf(fmaf(v.z, sc, sh), 0.0f);
    v.w = fmaxf(fmaf(v.w, sc, sh), 0.0f);
    ((float4*)y)[i] = v;
}

// ============================================================================
extern "C" void kernel_launch(void* const* d_in, const int* in_sizes, int n_in,
                              void* d_out, int out_size) {
    const float* xyzc  = (const float*)d_in[0];  // [2, 4096, 3]
    const float* fc    = (const float*)d_in[1];  // [2, 256, 4096]
    const float* xyzf  = (const float*)d_in[2];  // [2, 16384, 3]
    const float* ff    = (const float*)d_in[3];  // [2, 128, 16384]
    const float* W     = (const float*)d_in[4];  // [256, 384]
    const float* gamma = (const float*)d_in[5];  // [256]
    const float* beta  = (const float*)d_in[6];  // [256]
    float* out = (float*)d_out;                  // [2, 256, 16384]

    (void)in_sizes; (void)n_in; (void)out_size;

    static bool attr_done = false;
    if (!attr_done) {
        cudaFuncSetAttribute(fusedB_kernel,
                             cudaFuncAttributeMaxDynamicSharedMemorySize, SMEM_BYTES);
        cudaFuncSetAttribute(gemmC_kernel,
                             cudaFuncAttributeMaxDynamicSharedMemorySize, SMEM_BYTES);
        attr_done = true;
    }

    // K_A: nn partials + operand splits (independent, co-scheduled)
    fusedA_kernel<<<NN_BLOCKS + SPLIT_BLOCKS, 256>>>(xyzc, xyzf, W, ff, fc);

    // K_B: coarse GEMM + nn combine (independent, co-scheduled)
    fusedB_kernel<<<256, 256, SMEM_BYTES>>>(out);

    // K_C: fine GEMM + gather + BN partials
    gemmC_kernel<<<dim3(128, 2, 2), 256, SMEM_BYTES>>>(out);

    stats2_kernel<<<CO / 8, 256>>>(gamma, beta);
    norm_kernel<<<(BATCH * CO * NF / 4) / 256, 256>>>(out);
}

// round 13
// speedup vs baseline: 1.1105x; 1.0452x over previous
#include <cuda_runtime.h>
#include <cuda_bf16.h>
#include <cstdint>

#define BATCH 2
#define NC 4096
#define NF 16384
#define CC 256
#define CF 128
#define CO 256
#define KTOT 384  // CC + CF
#define NBLKF (NF / 128)

// NN config: 2 points/thread, 256-pt chunks -> 1024 blocks for occupancy
#define NN_TPB 256
#define NN_PPT 2
#define NN_PTS (NN_TPB * NN_PPT)      // 512 fine points per block
#define NN_CHK 256
#define NN_NCHUNK (NC / NN_CHK)       // 16
#define NN_FBLK (NF / NN_PTS)         // 32
#define NN_BLOCKS (NN_FBLK * NN_NCHUNK * BATCH)  // 1024

// split work (float4 counts)
#define W_F4   (CO * KTOT / 4)
#define FF_F4  (BATCH * CF * NF / 4)
#define FC_F4  (BATCH * CC * NC / 4)
#define SPLIT_F4 (W_F4 + FF_F4 + FC_F4)
#define SPLIT_BLOCKS (SPLIT_F4 / 1024)            // 1560

typedef unsigned long long u64;

// ---------------- scratch (device globals; no allocations allowed) ----------
__device__ float g_Yc[BATCH * CO * NC];
__device__ int   g_idx[BATCH * NF];
__device__ u64   g_nn_part[BATCH * NN_NCHUNK * NF];
__device__ float g_ps [BATCH * CO * NBLKF];
__device__ float g_pss[BATCH * CO * NBLKF];
__device__ __nv_bfloat16 g_Whi[CO * KTOT];
__device__ __nv_bfloat16 g_Wlo[CO * KTOT];
__device__ __nv_bfloat16 g_Ffh[BATCH * CF * NF];
__device__ __nv_bfloat16 g_Ffl[BATCH * CF * NF];
__device__ __nv_bfloat16 g_Fch[BATCH * CC * NC];
__device__ __nv_bfloat16 g_Fcl[BATCH * CC * NC];

// ---------------- helpers ----------------------------------------------------
__device__ __forceinline__ uint32_t smem_u32(const void* p) {
    uint32_t a;
    asm("{ .reg .u64 t; cvta.to.shared.u64 t, %1; cvt.u32.u64 %0, t; }"
        : "=r"(a) : "l"(p));
    return a;
}
__device__ __forceinline__ void cp16(uint32_t dst, const void* src) {
    asm volatile("cp.async.cg.shared.global [%0], [%1], 16;"
                 :: "r"(dst), "l"(src));
}
#define CP_COMMIT() asm volatile("cp.async.commit_group;" ::: "memory")
#define CP_WAIT1()  asm volatile("cp.async.wait_group 1;" ::: "memory")
#define CP_WAIT0()  asm volatile("cp.async.wait_group 0;" ::: "memory")

__device__ __forceinline__ void ldsm4(uint32_t (&r)[4], uint32_t addr) {
    asm volatile("ldmatrix.sync.aligned.m8n8.x4.shared.b16 {%0,%1,%2,%3}, [%4];"
                 : "=r"(r[0]), "=r"(r[1]), "=r"(r[2]), "=r"(r[3]) : "r"(addr));
}
__device__ __forceinline__ void ldsm4t(uint32_t (&r)[4], uint32_t addr) {
    asm volatile("ldmatrix.sync.aligned.m8n8.x4.trans.shared.b16 {%0,%1,%2,%3}, [%4];"
                 : "=r"(r[0]), "=r"(r[1]), "=r"(r[2]), "=r"(r[3]) : "r"(addr));
}
__device__ __forceinline__ void mma16816(float (&d)[4], const uint32_t (&a)[4],
                                         uint32_t b0, uint32_t b1) {
    asm volatile(
        "mma.sync.aligned.m16n8k16.row.col.f32.bf16.bf16.f32 "
        "{%0,%1,%2,%3}, {%4,%5,%6,%7}, {%8,%9}, {%0,%1,%2,%3};"
        : "+f"(d[0]), "+f"(d[1]), "+f"(d[2]), "+f"(d[3])
        : "r"(a[0]), "r"(a[1]), "r"(a[2]), "r"(a[3]), "r"(b0), "r"(b1));
}

__device__ __forceinline__ void split2(float x0, float x1, uint32_t& hi, uint32_t& lo) {
    __nv_bfloat16 h0 = __float2bfloat16(x0);
    __nv_bfloat16 h1 = __float2bfloat16(x1);
    float r0 = x0 - __bfloat162float(h0);
    float r1 = x1 - __bfloat162float(h1);
    __nv_bfloat162 hh;
    hh.x = h0; hh.y = h1;
    __nv_bfloat162 ll;
    ll.x = __float2bfloat16(r0); ll.y = __float2bfloat16(r1);
    hi = *(uint32_t*)&hh;
    lo = *(uint32_t*)&ll;
}

__device__ __forceinline__ uint32_t fkey(float d) {
    uint32_t u = __float_as_uint(d);
    return (u & 0x80000000u) ? ~u : (u | 0x80000000u);
}
__device__ __forceinline__ u64 packdi(float d, int idx) {
    return ((u64)fkey(d) << 32) | (uint32_t)idx;
}

// ============================================================================
// GEMM body: out[b,m,n] = sum_k W[m,WOFF+k]*F[b,k,n]; bf16 split, cp.async.
// ============================================================================
#define AROW 40
#define BROW 136
#define OFF_AH 0
#define OFF_AL 10240
#define OFF_BH 20480
#define OFF_BL 29184
#define BUFSZ 37888
#define OSTR 132
#define SMEM_BYTES (2 * BUFSZ + 512)

template <int N, int KDIM, int WOFF, bool GATHER>
__device__ __forceinline__ void gemm_body(int nb, int mb, int bb,
                                          float* __restrict__ dout, char* smp) {
    const uint32_t sb = smem_u32(smp);
    int* sidx = (int*)(smp + 2 * BUFSZ);
    constexpr int NCH = KDIM / 32;

    const int b = bb;
    const int mBase = mb * 128;
    const int nBase = nb * 128;
    const int t = threadIdx.x;
    const int w = t >> 5;
    const int lid = t & 31;
    const int wm = (w >> 1) * 32;
    const int wn = (w & 1) * 64;

    if (GATHER && t < 128) sidx[t] = g_idx[b * NF + nBase + t];

    const __nv_bfloat16* Ahi = g_Whi;
    const __nv_bfloat16* Alo = g_Wlo;
    const __nv_bfloat16* Bhi = GATHER ? g_Ffh : g_Fch;
    const __nv_bfloat16* Blo = GATHER ? g_Ffl : g_Fcl;

    float c[2][8][4];
#pragma unroll
    for (int mt = 0; mt < 2; mt++)
#pragma unroll
        for (int nt = 0; nt < 8; nt++)
#pragma unroll
            for (int r = 0; r < 4; r++) c[mt][nt][r] = 0.f;

    const char* Abh = (const char*)(Ahi + (size_t)mBase * KTOT + WOFF);
    const char* Abl = (const char*)(Alo + (size_t)mBase * KTOT + WOFF);
    const char* Bbh = (const char*)(Bhi + ((size_t)b * KDIM) * N + nBase);
    const char* Bbl = (const char*)(Blo + ((size_t)b * KDIM) * N + nBase);

    const int ar0 = t >> 2;
    const int ac0 = t & 3;
    const int br0 = t >> 4;
    const int bc0 = t & 15;

    const int a_row = (lid & 7) + ((lid >> 3) & 1) * 8;
    const int a_colb = (lid >> 4) * 8;
    const int b_row = (lid & 7) + ((lid >> 3) & 1) * 8;
    const int b_colb = (lid >> 4) * 8;

    auto issue = [&](int s, int k0) {
        const uint32_t st = sb + s * BUFSZ;
#pragma unroll
        for (int p = 0; p < 2; p++) {
            const int row = ar0 + p * 64;
            const int col = ac0;
            cp16(st + OFF_AH + row * 80 + col * 16,
                 Abh + (size_t)row * (KTOT * 2) + k0 * 2 + col * 16);
            cp16(st + OFF_AL + row * 80 + col * 16,
                 Abl + (size_t)row * (KTOT * 2) + k0 * 2 + col * 16);
        }
#pragma unroll
        for (int p = 0; p < 2; p++) {
            const int k = br0 + p * 16;
            const int col = bc0;
            cp16(st + OFF_BH + k * 272 + col * 16,
                 Bbh + (size_t)(k0 + k) * (N * 2) + col * 16);
            cp16(st + OFF_BL + k * 272 + col * 16,
                 Bbl + (size_t)(k0 + k) * (N * 2) + col * 16);
        }
    };

    issue(0, 0);
    CP_COMMIT();

#pragma unroll
    for (int ck = 0; ck < NCH; ck++) {
        if (ck + 1 < NCH) {
            issue((ck + 1) & 1, (ck + 1) * 32);
            CP_COMMIT();
            CP_WAIT1();
        } else {
            CP_WAIT0();
        }
        __syncthreads();

        const uint32_t cb = sb + (ck & 1) * BUFSZ;
#pragma unroll
        for (int k16 = 0; k16 < 2; k16++) {
            uint32_t ah[2][4], al[2][4], bh[4][4], bl[4][4];
#pragma unroll
            for (int mt = 0; mt < 2; mt++) {
                uint32_t ad = cb + ((wm + mt * 16 + a_row) * AROW + k16 * 16 + a_colb) * 2;
                ldsm4(ah[mt], ad + OFF_AH);
                ldsm4(al[mt], ad + OFF_AL);
            }
#pragma unroll
            for (int ng = 0; ng < 4; ng++) {
                uint32_t bd = cb + ((k16 * 16 + b_row) * BROW + wn + ng * 16 + b_colb) * 2;
                ldsm4t(bh[ng], bd + OFF_BH);
                ldsm4t(bl[ng], bd + OFF_BL);
            }
#pragma unroll
            for (int mt = 0; mt < 2; mt++)
#pragma unroll
                for (int nt = 0; nt < 8; nt++) {
                    const int ng = nt >> 1;
                    const int pr = (nt & 1) * 2;
                    mma16816(c[mt][nt], ah[mt], bh[ng][pr], bh[ng][pr + 1]);
                    mma16816(c[mt][nt], ah[mt], bl[ng][pr], bl[ng][pr + 1]);
                    mma16816(c[mt][nt], al[mt], bh[ng][pr], bh[ng][pr + 1]);
                }
        }
        __syncthreads();
    }

    float* smOut = (float*)smp;
    {
        const int r_m = lid >> 2;
        const int cn = (lid & 3) * 2;
#pragma unroll
        for (int mt = 0; mt < 2; mt++)
#pragma unroll
            for (int nt = 0; nt < 8; nt++) {
                const int row = wm + mt * 16 + r_m;
                const int col = wn + nt * 8 + cn;
                *(float2*)&smOut[row * OSTR + col] =
                    make_float2(c[mt][nt][0], c[mt][nt][1]);
                *(float2*)&smOut[(row + 8) * OSTR + col] =
                    make_float2(c[mt][nt][2], c[mt][nt][3]);
            }
    }
    __syncthreads();

#pragma unroll 4
    for (int rr = 0; rr < 16; rr++) {
        const int r0 = w + rr * 8;
        const int m = mBase + r0;
        float4 v = *(float4*)&smOut[r0 * OSTR + lid * 4];
        if (GATHER) {
            const float* yc = g_Yc + ((size_t)b * CO + m) * NC;
            v.x += yc[sidx[lid * 4 + 0]];
            v.y += yc[sidx[lid * 4 + 1]];
            v.z += yc[sidx[lid * 4 + 2]];
            v.w += yc[sidx[lid * 4 + 3]];
            *(float4*)&dout[((size_t)b * CO + m) * NF + nBase + lid * 4] = v;
            float s = v.x + v.y + v.z + v.w;
            float ss = v.x * v.x + v.y * v.y + v.z * v.z + v.w * v.w;
#pragma unroll
            for (int off = 16; off > 0; off >>= 1) {
                s += __shfl_down_sync(0xffffffffu, s, off);
                ss += __shfl_down_sync(0xffffffffu, ss, off);
            }
            if (lid == 0) {
                g_ps [((size_t)b * CO + m) * NBLKF + nb] = s;
                g_pss[((size_t)b * CO + m) * NBLKF + nb] = ss;
            }
        } else {
            *(float4*)&g_Yc[((size_t)b * CO + m) * NC + nBase + lid * 4] = v;
        }
    }
}

// ============================================================================
// K_A: fused nn_part (blocks 0..1023) + operand splits (blocks 1024..)
// ============================================================================
__global__ __launch_bounds__(256) void fusedA_kernel(
    const float* __restrict__ xyzc, const float* __restrict__ xyzf,
    const float* __restrict__ W, const float* __restrict__ ff,
    const float* __restrict__ fc) {
    const int bid = blockIdx.x;
    const int t = threadIdx.x;

    if (bid < NN_BLOCKS) {
        // ---- NN partial argmin: bid = fblk | chunk<<5 | b<<9
        __shared__ float4 sc[NN_CHK];
        const int fblk = bid & (NN_FBLK - 1);
        const int chunk = (bid >> 5) & (NN_NCHUNK - 1);
        const int b = bid >> 9;
        const int fbase = fblk * NN_PTS + t;

        float px[NN_PPT], py[NN_PPT], pz[NN_PPT];
#pragma unroll
        for (int p = 0; p < NN_PPT; p++) {
            const float* pp = xyzf + ((size_t)b * NF + fbase + p * NN_TPB) * 3;
            px[p] = -2.0f * pp[0];
            py[p] = -2.0f * pp[1];
            pz[p] = -2.0f * pp[2];
        }
        {
            const float* c = xyzc + ((size_t)b * NC + chunk * NN_CHK + t) * 3;
            float x = c[0], y = c[1], z = c[2];
            sc[t] = make_float4(x, y, z, x * x + y * y + z * z);
        }
        __syncthreads();

        float best[NN_PPT];
        int bi[NN_PPT];
#pragma unroll
        for (int p = 0; p < NN_PPT; p++) {
            best[p] = 3.4e38f;
            bi[p] = 0;
        }

#pragma unroll 2
        for (int j = 0; j < NN_CHK; j += 4) {
            float4 c0 = sc[j];
            float4 c1 = sc[j + 1];
            float4 c2 = sc[j + 2];
            float4 c3 = sc[j + 3];
#pragma unroll
            for (int p = 0; p < NN_PPT; p++) {
                float d0 = fmaf(pz[p], c0.z, fmaf(py[p], c0.y, fmaf(px[p], c0.x, c0.w)));
                float d1 = fmaf(pz[p], c1.z, fmaf(py[p], c1.y, fmaf(px[p], c1.x, c1.w)));
                float d2 = fmaf(pz[p], c2.z, fmaf(py[p], c2.y, fmaf(px[p], c2.x, c2.w)));
                float d3 = fmaf(pz[p], c3.z, fmaf(py[p], c3.y, fmaf(px[p], c3.x, c3.w)));
                float m = fminf(fminf(d0, d1), fminf(d2, d3));
                if (m < best[p]) {
                    best[p] = m;
                    int jj = (d0 == m) ? 0 : (d1 == m) ? 1 : (d2 == m) ? 2 : 3;
                    bi[p] = j + jj;
                }
            }
        }

        const int cbase = chunk * NN_CHK;
        u64* part = g_nn_part + ((size_t)b * NN_NCHUNK + chunk) * NF;
#pragma unroll
        for (int p = 0; p < NN_PPT; p++)
            part[fbase + p * NN_TPB] = packdi(best[p], cbase + bi[p]);
    } else {
        // ---- fp32 -> bf16 hi/lo splits
        const size_t base = (size_t)(bid - NN_BLOCKS) * 1024 + t;
#pragma unroll
        for (int r = 0; r < 4; r++) {
            size_t i = base + (size_t)r * 256;
            const float4* src;
            uint2* hi;
            uint2* lo;
            size_t off;
            if (i < W_F4) {
                src = (const float4*)W; hi = (uint2*)g_Whi; lo = (uint2*)g_Wlo;
                off = i;
            } else if (i < W_F4 + FF_F4) {
                src = (const float4*)ff; hi = (uint2*)g_Ffh; lo = (uint2*)g_Ffl;
                off = i - W_F4;
            } else {
                src = (const float4*)fc; hi = (uint2*)g_Fch; lo = (uint2*)g_Fcl;
                off = i - W_F4 - FF_F4;
            }
            float4 v = src[off];
            uint32_t h0, l0, h1, l1;
            split2(v.x, v.y, h0, l0);
            split2(v.z, v.w, h1, l1);
            hi[off] = make_uint2(h0, h1);
            lo[off] = make_uint2(l0, l1);
        }
    }
}

// ============================================================================
// K_B: fused coarse GEMM (blocks 0..127) + nn_combine (blocks 128..255)
// ============================================================================
__global__ __launch_bounds__(256) void fusedB_kernel(float* __restrict__ dout) {
    extern __shared__ char smp[];
    const int bid = blockIdx.x;
    if (bid < 128) {
        gemm_body<NC, CC, 0, false>(bid & 31, (bid >> 5) & 1, bid >> 6, dout, smp);
    } else {
        const int i = (bid - 128) * 256 + threadIdx.x;  // over B*NF
        const int b = i >> 14;
        const int f = i & (NF - 1);
        const u64* part = g_nn_part + (size_t)b * NN_NCHUNK * NF + f;
        u64 best = part[0];
#pragma unroll
        for (int c = 1; c < NN_NCHUNK; c++) {
            u64 v = part[(size_t)c * NF];
            best = (v < best) ? v : best;
        }
        g_idx[i] = (int)(best & 0xFFFFFFFFu);
    }
}

// ============================================================================
// K_C: fine GEMM + gather + BN partials
// ============================================================================
__global__ __launch_bounds__(256) void gemmC_kernel(float* __restrict__ dout) {
    extern __shared__ char smp[];
    gemm_body<NF, CF, CC, true>(blockIdx.x, blockIdx.y, blockIdx.z, dout, smp);
}

// ============================================================================
// K_D: fused BN-finish + normalize + relu. One block = 256 float4 of ONE
// channel; each block re-reduces its channel's 256 partials (L2-hot), then
// normalizes its 4KB segment in place. Deterministic.
// ============================================================================
__global__ __launch_bounds__(256) void norm_fused_kernel(
    float* __restrict__ y, const float* __restrict__ gamma,
    const float* __restrict__ beta) {
    const int blk = blockIdx.x;
    const int o = (blk >> 4) & (CO - 1);
    const int t = threadIdx.x;
    const int w = t >> 5;
    const int lane = t & 31;

    size_t off = ((size_t)(t >> 7) * CO + o) * NBLKF + (t & 127);
    float s = g_ps[off];
    float ss = g_pss[off];
#pragma unroll
    for (int d = 16; d > 0; d >>= 1) {
        s += __shfl_down_sync(0xffffffffu, s, d);
        ss += __shfl_down_sync(0xffffffffu, ss, d);
    }
    __shared__ float as[8], as2[8], bc[2];
    if (lane == 0) {
        as[w] = s;
        as2[w] = ss;
    }
    __syncthreads();
    if (t == 0) {
        float S = 0.f, SS = 0.f;
#pragma unroll
        for (int i = 0; i < 8; i++) {
            S += as[i];
            SS += as2[i];
        }
        const float invn = 1.0f / (BATCH * NF);
        float mean = S * invn;
        float var = SS * invn - mean * mean;
        var = fmaxf(var, 0.0f);
        float r = rsqrtf(var + 1e-5f);
        float sc = gamma[o] * r;
        bc[0] = sc;
        bc[1] = beta[o] - mean * sc;
    }
    __syncthreads();
    const float sc = bc[0];
    const float sh = bc[1];

    float4* y4 = (float4*)y;
    const size_t i = (size_t)blk * 256 + t;
    float4 v = y4[i];
    v.x = fmaxf(fmaf(v.x, sc, sh), 0.0f);
    v.y = fmaxf(fmaf(v.y, sc, sh), 0.0f);
    v.z = fmaxf(fmaf(v.z, sc, sh), 0.0f);
    v.w = fmaxf(fmaf(v.w, sc, sh), 0.0f);
    y4[i] = v;
}

// ============================================================================
extern "C" void kernel_launch(void* const* d_in, const int* in_sizes, int n_in,
                              void* d_out, int out_size) {
    const float* xyzc  = (const float*)d_in[0];  // [2, 4096, 3]
    const float* fc    = (const float*)d_in[1];  // [2, 256, 4096]
    const float* xyzf  = (const float*)d_in[2];  // [2, 16384, 3]
    const float* ff    = (const float*)d_in[3];  // [2, 128, 16384]
    const float* W     = (const float*)d_in[4];  // [256, 384]
    const float* gamma = (const float*)d_in[5];  // [256]
    const float* beta  = (const float*)d_in[6];  // [256]
    float* out = (float*)d_out;                  // [2, 256, 16384]

    (void)in_sizes; (void)n_in; (void)out_size;

    static bool attr_done = false;
    if (!attr_done) {
        cudaFuncSetAttribute(fusedB_kernel,
                             cudaFuncAttributeMaxDynamicSharedMemorySize, SMEM_BYTES);
        cudaFuncSetAttribute(gemmC_kernel,
                             cudaFuncAttributeMaxDynamicSharedMemorySize, SMEM_BYTES);
        attr_done = true;
    }

    // K_A: nn partials (1024 blocks) + operand splits (co-scheduled)
    fusedA_kernel<<<NN_BLOCKS + SPLIT_BLOCKS, 256>>>(xyzc, xyzf, W, ff, fc);

    // K_B: coarse GEMM + nn combine (co-scheduled)
    fusedB_kernel<<<256, 256, SMEM_BYTES>>>(out);

    // K_C: fine GEMM + gather + BN partials
    gemmC_kernel<<<dim3(128, 2, 2), 256, SMEM_BYTES>>>(out);

    // K_D: BN finish + normalize + relu (fused)
    norm_fused_kernel<<<BATCH * CO * NF / 1024, 256>>>(out, gamma, beta);
}